// round 14
// baseline (speedup 1.0000x reference)
#include <cuda_runtime.h>
#include <math.h>

#define KC 8
#define LV 8
#define TS (1u << 18)
#define FF 2
#define HID 64
#define ENC (LV * FF)              // 16
#define W1_STRIDE (ENC * HID + 4)  // 1028 floats: +4 skews banks per cluster
#define NT 256
#define NPTS 524288
#define SRX 64
#define SRYZ 128
#define NBINS (SRX * SRYZ * SRYZ)                // 1048576
#define NPART (NBINS / 256)                      // 4096

__device__ unsigned d_bins[NBINS];   // zero-init at load; self-cleaned by k_scan_c
__device__ unsigned d_offs[NBINS];
__device__ unsigned d_part[NPART];
__device__ float4   d_spos[NPTS];    // x, y, z, bitcast(origidx)

__device__ __forceinline__ unsigned cell_key(float x, float y, float z)
{
    unsigned cx = min((unsigned)(x * (float)SRX),  SRX  - 1u);
    unsigned cy = min((unsigned)(y * (float)SRYZ), SRYZ - 1u);
    unsigned cz = min((unsigned)(z * (float)SRYZ), SRYZ - 1u);
    return cx | (cy << 6) | (cz << 13);   // x fastest: hash-contiguity in x
}

__global__ void k_count(const float4* __restrict__ pos4, int N4)
{
    int t = blockIdx.x * blockDim.x + threadIdx.x;
    if (t >= N4) return;
    float4 a = __ldg(&pos4[t * 3 + 0]);
    float4 b = __ldg(&pos4[t * 3 + 1]);
    float4 c = __ldg(&pos4[t * 3 + 2]);
    atomicAdd(&d_bins[cell_key(a.x, a.y, a.z)], 1u);
    atomicAdd(&d_bins[cell_key(a.w, b.x, b.y)], 1u);
    atomicAdd(&d_bins[cell_key(b.z, b.w, c.x)], 1u);
    atomicAdd(&d_bins[cell_key(c.y, c.z, c.w)], 1u);
}

__global__ __launch_bounds__(256) void k_scan_a()
{
    __shared__ unsigned s[256];
    const int t = threadIdx.x;
    s[t] = d_bins[blockIdx.x * 256 + t];
    __syncthreads();
#pragma unroll
    for (int off = 128; off > 0; off >>= 1) {
        if (t < off) s[t] += s[t + off];
        __syncthreads();
    }
    if (t == 0) d_part[blockIdx.x] = s[0];
}

// Fused base-reduce + per-block exclusive scan; self-cleans d_bins.
__global__ __launch_bounds__(256) void k_scan_c()
{
    __shared__ unsigned s[256];
    __shared__ unsigned sbase[256];
    const int t = threadIdx.x;
    const int bid = blockIdx.x;

    unsigned acc = 0;
#pragma unroll 4
    for (int q = 0; q < NPART / 256; q++) {
        int i = q * 256 + t;
        if (i < bid) acc += d_part[i];
    }
    sbase[t] = acc;

    const unsigned v = d_bins[bid * 256 + t];
    d_bins[bid * 256 + t] = 0u;
    s[t] = v;
    __syncthreads();

#pragma unroll
    for (int off = 128; off > 0; off >>= 1) {
        if (t < off) sbase[t] += sbase[t + off];
        __syncthreads();
    }
    for (int off = 1; off < 256; off <<= 1) {
        unsigned u = (t >= off) ? s[t - off] : 0u;
        __syncthreads();
        s[t] += u;
        __syncthreads();
    }
    d_offs[bid * 256 + t] = s[t] - v + sbase[0];
}

__global__ void k_scatter(const float* __restrict__ positions, int N)
{
    int i = blockIdx.x * blockDim.x + threadIdx.x;
    if (i >= N) return;
    float x = positions[i * 3 + 0];
    float y = positions[i * 3 + 1];
    float z = positions[i * 3 + 2];
    unsigned slot = atomicAdd(&d_offs[cell_key(x, y, z)], 1u);
    d_spos[slot] = make_float4(x, y, z, __int_as_float(i));
}

// One trilinear-blended level for one point.
__device__ __forceinline__ void hash_level(
    const float2* __restrict__ tbl, unsigned lbase,
    float sx, float sy, float sz, float& e0, float& e1)
{
    const float fx = floorf(sx), fy = floorf(sy), fz = floorf(sz);
    const float wx = sx - fx, wy = sy - fy, wz = sz - fz;
    const unsigned x0 = (unsigned)fx, y0 = (unsigned)fy, z0 = (unsigned)fz;
    const unsigned hy0 = y0 * 2654435761u, hy1 = (y0 + 1u) * 2654435761u;
    const unsigned hz0 = z0 * 805459861u,  hz1 = (z0 + 1u) * 805459861u;
    const bool xeven = (x0 & 1u) == 0u;
    const unsigned hxor = x0 ^ (x0 + 1u);

    e0 = 0.0f; e1 = 0.0f;
#pragma unroll
    for (int c = 0; c < 4; c++) {
        const unsigned hy = (c & 2) ? hy1 : hy0;
        const unsigned hz = (c & 1) ? hz1 : hz0;
        const unsigned a = (x0 ^ hy ^ hz) & (TS - 1u);

        float2 f0, f1;
        if (xeven) {
            const float4 q = __ldg(reinterpret_cast<const float4*>(
                tbl + lbase + (a & ~1u)));
            const bool hi = (a & 1u) != 0u;
            f0.x = hi ? q.z : q.x;  f0.y = hi ? q.w : q.y;
            f1.x = hi ? q.x : q.z;  f1.y = hi ? q.y : q.w;
        } else {
            f0 = __ldg(&tbl[lbase + a]);
            f1 = __ldg(&tbl[lbase + (a ^ hxor)]);
        }

        const float cwy = (c & 2) ? wy : 1.0f - wy;
        const float cwz = (c & 1) ? wz : 1.0f - wz;
        const float cwyz = cwy * cwz;
        const float cw0 = (1.0f - wx) * cwyz;
        const float cw1 = wx * cwyz;
        e0 = fmaf(f0.x, cw0, fmaf(f1.x, cw1, e0));
        e1 = fmaf(f0.y, cw0, fmaf(f1.y, cw1, e1));
    }
}

__device__ __forceinline__ int argmin_k(const float* sc, float px, float py, float pz)
{
    int kbest = 0;
    float dbest = 3.4e38f;
#pragma unroll
    for (int k = 0; k < KC; k++) {
        float dx = px - sc[k * 3 + 0];
        float dy = py - sc[k * 3 + 1];
        float dz = pz - sc[k * 3 + 2];
        float d = dx * dx + dy * dy + dz * dz;
        if (d < dbest) { dbest = d; kbest = k; }
    }
    return kbest;
}

__device__ __forceinline__ float mlp_eval(
    const float* __restrict__ sW1, const float* __restrict__ sb1,
    const float* __restrict__ sW2, const float* __restrict__ sb2,
    int kbest, const float* enc)
{
    const float* w1k = sW1 + kbest * W1_STRIDE;
    const float* b1k = sb1 + kbest * HID;
    const float* w2k = sW2 + kbest * HID;
    float dens = sb2[kbest];

#pragma unroll
    for (int jc = 0; jc < HID / 16; jc++) {
        float4 h4[4];
#pragma unroll
        for (int q = 0; q < 4; q++)
            h4[q] = *reinterpret_cast<const float4*>(b1k + jc * 16 + q * 4);
#pragma unroll
        for (int i = 0; i < ENC; i++) {
            const float e = enc[i];
#pragma unroll
            for (int q = 0; q < 4; q++) {
                const float4 w = *reinterpret_cast<const float4*>(
                    w1k + i * HID + jc * 16 + q * 4);
                h4[q].x = fmaf(e, w.x, h4[q].x);
                h4[q].y = fmaf(e, w.y, h4[q].y);
                h4[q].z = fmaf(e, w.z, h4[q].z);
                h4[q].w = fmaf(e, w.w, h4[q].w);
            }
        }
#pragma unroll
        for (int q = 0; q < 4; q++) {
            const float4 w2 = *reinterpret_cast<const float4*>(w2k + jc * 16 + q * 4);
            dens = fmaf(fmaxf(h4[q].x, 0.0f), w2.x, dens);
            dens = fmaf(fmaxf(h4[q].y, 0.0f), w2.y, dens);
            dens = fmaf(fmaxf(h4[q].z, 0.0f), w2.z, dens);
            dens = fmaf(fmaxf(h4[q].w, 0.0f), w2.w, dens);
        }
    }
    return dens;
}

// 2 points per thread: level-interleaved gathers double the outstanding-load
// window; MLP evaluated per point afterwards.
__global__ __launch_bounds__(NT, 3)
void density_kernel(const float* __restrict__ centroids,
                    const float* __restrict__ tables,
                    const float* __restrict__ W1,
                    const float* __restrict__ b1,
                    const float* __restrict__ W2,
                    const float* __restrict__ b2,
                    float* __restrict__ out, int N)
{
    __shared__ float sW1[KC * W1_STRIDE];
    __shared__ float sb1[KC * HID];
    __shared__ float sW2[KC * HID];
    __shared__ float sb2[KC];
    __shared__ float sc[KC * 3];

    const int tid = threadIdx.x;

    for (int i = tid; i < KC * ENC * HID; i += NT) {
        int k = i / (ENC * HID);
        int r = i - k * (ENC * HID);
        sW1[k * W1_STRIDE + r] = W1[i];
    }
    for (int i = tid; i < KC * HID; i += NT) {
        sb1[i] = b1[i];
        sW2[i] = W2[i];
    }
    if (tid < KC) sb2[tid] = b2[tid];
    if (tid < KC * 3) sc[tid] = centroids[tid];
    __syncthreads();

    const int idxA = blockIdx.x * (2 * NT) + tid;
    const int idxB = idxA + NT;
    if (idxA >= N) return;
    const bool hasB = idxB < N;

    const float4 pA = d_spos[idxA];
    const float4 pB = d_spos[hasB ? idxB : idxA];

    const int kA = argmin_k(sc, pA.x, pA.y, pA.z);
    const int kB = argmin_k(sc, pB.x, pB.y, pB.z);

    const float2* tbl = reinterpret_cast<const float2*>(tables);
    const unsigned kbaseA = (unsigned)kA * LV;
    const unsigned kbaseB = (unsigned)kB * LV;

    float encA[ENC], encB[ENC];
    float res = 16.0f;
#pragma unroll
    for (int l = 0; l < LV; l++) {
        float a0, a1, b0, b1v;
        hash_level(tbl, (kbaseA + l) * TS, pA.x * res, pA.y * res, pA.z * res, a0, a1);
        hash_level(tbl, (kbaseB + l) * TS, pB.x * res, pB.y * res, pB.z * res, b0, b1v);
        encA[2 * l + 0] = a0;  encA[2 * l + 1] = a1;
        encB[2 * l + 0] = b0;  encB[2 * l + 1] = b1v;
        res *= 2.0f;
    }

    const float dA = mlp_eval(sW1, sb1, sW2, sb2, kA, encA);
    out[__float_as_int(pA.w)] = __expf(dA);
    if (hasB) {
        const float dB = mlp_eval(sW1, sb1, sW2, sb2, kB, encB);
        out[__float_as_int(pB.w)] = __expf(dB);
    }
}

extern "C" void kernel_launch(void* const* d_in, const int* in_sizes, int n_in,
                              void* d_out, int out_size)
{
    const float* positions = (const float*)d_in[0];
    const float* centroids = (const float*)d_in[1];
    const float* tables    = (const float*)d_in[2];
    const float* W1        = (const float*)d_in[3];
    const float* b1        = (const float*)d_in[4];
    const float* W2        = (const float*)d_in[5];
    const float* b2        = (const float*)d_in[6];
    float* out = (float*)d_out;

    const int N = in_sizes[0] / 3;
    const int N4 = N / 4;   // N = 524288, divisible by 4

    k_count<<<(N4 + 255) / 256, 256>>>((const float4*)positions, N4);
    k_scan_a<<<NPART, 256>>>();
    k_scan_c<<<NPART, 256>>>();
    k_scatter<<<(N + 255) / 256, 256>>>(positions, N);
    density_kernel<<<(N + 2 * NT - 1) / (2 * NT), NT>>>(centroids, tables,
                                                        W1, b1, W2, b2, out, N);
}

// round 15
// speedup vs baseline: 1.2553x; 1.2553x over previous
#include <cuda_runtime.h>
#include <math.h>

#define KC 8
#define LV 8
#define TS (1u << 18)
#define FF 2
#define HID 64
#define ENC (LV * FF)              // 16
#define W1_STRIDE (ENC * HID + 4)  // 1028 floats: +4 skews banks per cluster
#define NT 256
#define NPTS 524288
#define SORT_RES 64
#define NBINS (SORT_RES * SORT_RES * SORT_RES)   // 262144
#define NPART 1024                               // NBINS / 256

__device__ unsigned d_bins[NBINS];   // zero-init at load; self-cleaned by k_scan_c
__device__ unsigned d_offs[NBINS];
__device__ unsigned d_part[NPART];
__device__ float4   d_spos[NPTS];    // x, y, z, bitcast(origidx)

__device__ __forceinline__ unsigned cell_key(float x, float y, float z)
{
    unsigned cx = min((unsigned)(x * (float)SORT_RES), SORT_RES - 1u);
    unsigned cy = min((unsigned)(y * (float)SORT_RES), SORT_RES - 1u);
    unsigned cz = min((unsigned)(z * (float)SORT_RES), SORT_RES - 1u);
    return cx | (cy << 6) | (cz << 12);   // x fastest: hash-contiguity in x
}

__global__ void k_count(const float4* __restrict__ pos4, int N4)
{
    int t = blockIdx.x * blockDim.x + threadIdx.x;
    if (t >= N4) return;
    float4 a = __ldg(&pos4[t * 3 + 0]);
    float4 b = __ldg(&pos4[t * 3 + 1]);
    float4 c = __ldg(&pos4[t * 3 + 2]);
    atomicAdd(&d_bins[cell_key(a.x, a.y, a.z)], 1u);
    atomicAdd(&d_bins[cell_key(a.w, b.x, b.y)], 1u);
    atomicAdd(&d_bins[cell_key(b.z, b.w, c.x)], 1u);
    atomicAdd(&d_bins[cell_key(c.y, c.z, c.w)], 1u);
}

__global__ __launch_bounds__(256) void k_scan_a()
{
    __shared__ unsigned s[256];
    const int t = threadIdx.x;
    s[t] = d_bins[blockIdx.x * 256 + t];
    __syncthreads();
#pragma unroll
    for (int off = 128; off > 0; off >>= 1) {
        if (t < off) s[t] += s[t + off];
        __syncthreads();
    }
    if (t == 0) d_part[blockIdx.x] = s[0];
}

// Fused base-reduce + per-block exclusive scan; self-cleans d_bins.
__global__ __launch_bounds__(256) void k_scan_c()
{
    __shared__ unsigned s[256];
    __shared__ unsigned sbase[256];
    const int t = threadIdx.x;
    const int bid = blockIdx.x;

    unsigned acc = 0;
#pragma unroll
    for (int q = 0; q < NPART / 256; q++) {
        int i = q * 256 + t;
        if (i < bid) acc += d_part[i];
    }
    sbase[t] = acc;

    const unsigned v = d_bins[bid * 256 + t];
    d_bins[bid * 256 + t] = 0u;
    s[t] = v;
    __syncthreads();

#pragma unroll
    for (int off = 128; off > 0; off >>= 1) {
        if (t < off) sbase[t] += sbase[t + off];
        __syncthreads();
    }
    for (int off = 1; off < 256; off <<= 1) {
        unsigned u = (t >= off) ? s[t - off] : 0u;
        __syncthreads();
        s[t] += u;
        __syncthreads();
    }
    d_offs[bid * 256 + t] = s[t] - v + sbase[0];
}

__global__ void k_scatter(const float* __restrict__ positions, int N)
{
    int i = blockIdx.x * blockDim.x + threadIdx.x;
    if (i >= N) return;
    float x = positions[i * 3 + 0];
    float y = positions[i * 3 + 1];
    float z = positions[i * 3 + 2];
    unsigned slot = atomicAdd(&d_offs[cell_key(x, y, z)], 1u);
    d_spos[slot] = make_float4(x, y, z, __int_as_float(i));
}

// One trilinear-blended level for one point.
__device__ __forceinline__ void hash_level(
    const float2* __restrict__ tbl, unsigned lbase,
    float sx, float sy, float sz, float& e0, float& e1)
{
    const float fx = floorf(sx), fy = floorf(sy), fz = floorf(sz);
    const float wx = sx - fx, wy = sy - fy, wz = sz - fz;
    const unsigned x0 = (unsigned)fx, y0 = (unsigned)fy, z0 = (unsigned)fz;
    const unsigned hy0 = y0 * 2654435761u, hy1 = (y0 + 1u) * 2654435761u;
    const unsigned hz0 = z0 * 805459861u,  hz1 = (z0 + 1u) * 805459861u;
    const bool xeven = (x0 & 1u) == 0u;
    const unsigned hxor = x0 ^ (x0 + 1u);

    e0 = 0.0f; e1 = 0.0f;
#pragma unroll
    for (int c = 0; c < 4; c++) {
        const unsigned hy = (c & 2) ? hy1 : hy0;
        const unsigned hz = (c & 1) ? hz1 : hz0;
        const unsigned a = (x0 ^ hy ^ hz) & (TS - 1u);

        float2 f0, f1;
        if (xeven) {
            const float4 q = __ldg(reinterpret_cast<const float4*>(
                tbl + lbase + (a & ~1u)));
            const bool hi = (a & 1u) != 0u;
            f0.x = hi ? q.z : q.x;  f0.y = hi ? q.w : q.y;
            f1.x = hi ? q.x : q.z;  f1.y = hi ? q.y : q.w;
        } else {
            f0 = __ldg(&tbl[lbase + a]);
            f1 = __ldg(&tbl[lbase + (a ^ hxor)]);
        }

        const float cwy = (c & 2) ? wy : 1.0f - wy;
        const float cwz = (c & 1) ? wz : 1.0f - wz;
        const float cwyz = cwy * cwz;
        const float cw0 = (1.0f - wx) * cwyz;
        const float cw1 = wx * cwyz;
        e0 = fmaf(f0.x, cw0, fmaf(f1.x, cw1, e0));
        e1 = fmaf(f0.y, cw0, fmaf(f1.y, cw1, e1));
    }
}

__device__ __forceinline__ int argmin_k(const float* sc, float px, float py, float pz)
{
    int kbest = 0;
    float dbest = 3.4e38f;
#pragma unroll
    for (int k = 0; k < KC; k++) {
        float dx = px - sc[k * 3 + 0];
        float dy = py - sc[k * 3 + 1];
        float dz = pz - sc[k * 3 + 2];
        float d = dx * dx + dy * dy + dz * dz;
        if (d < dbest) { dbest = d; kbest = k; }
    }
    return kbest;
}

__device__ __forceinline__ float mlp_eval(
    const float* __restrict__ sW1, const float* __restrict__ sb1,
    const float* __restrict__ sW2, const float* __restrict__ sb2,
    int kbest, const float* enc)
{
    const float* w1k = sW1 + kbest * W1_STRIDE;
    const float* b1k = sb1 + kbest * HID;
    const float* w2k = sW2 + kbest * HID;
    float dens = sb2[kbest];

#pragma unroll
    for (int jc = 0; jc < HID / 16; jc++) {
        float4 h4[4];
#pragma unroll
        for (int q = 0; q < 4; q++)
            h4[q] = *reinterpret_cast<const float4*>(b1k + jc * 16 + q * 4);
#pragma unroll
        for (int i = 0; i < ENC; i++) {
            const float e = enc[i];
#pragma unroll
            for (int q = 0; q < 4; q++) {
                const float4 w = *reinterpret_cast<const float4*>(
                    w1k + i * HID + jc * 16 + q * 4);
                h4[q].x = fmaf(e, w.x, h4[q].x);
                h4[q].y = fmaf(e, w.y, h4[q].y);
                h4[q].z = fmaf(e, w.z, h4[q].z);
                h4[q].w = fmaf(e, w.w, h4[q].w);
            }
        }
#pragma unroll
        for (int q = 0; q < 4; q++) {
            const float4 w2 = *reinterpret_cast<const float4*>(w2k + jc * 16 + q * 4);
            dens = fmaf(fmaxf(h4[q].x, 0.0f), w2.x, dens);
            dens = fmaf(fmaxf(h4[q].y, 0.0f), w2.y, dens);
            dens = fmaf(fmaxf(h4[q].z, 0.0f), w2.z, dens);
            dens = fmaf(fmaxf(h4[q].w, 0.0f), w2.w, dens);
        }
    }
    return dens;
}

// 2 points per thread; warp-contiguous A/B: each warp owns one 64-point
// span of the sorted order (A = first 32, B = next 32), so both gather
// streams share table cache lines within the warp.
__global__ __launch_bounds__(NT, 3)
void density_kernel(const float* __restrict__ centroids,
                    const float* __restrict__ tables,
                    const float* __restrict__ W1,
                    const float* __restrict__ b1,
                    const float* __restrict__ W2,
                    const float* __restrict__ b2,
                    float* __restrict__ out, int N)
{
    __shared__ float sW1[KC * W1_STRIDE];
    __shared__ float sb1[KC * HID];
    __shared__ float sW2[KC * HID];
    __shared__ float sb2[KC];
    __shared__ float sc[KC * 3];

    const int tid = threadIdx.x;

    for (int i = tid; i < KC * ENC * HID; i += NT) {
        int k = i / (ENC * HID);
        int r = i - k * (ENC * HID);
        sW1[k * W1_STRIDE + r] = W1[i];
    }
    for (int i = tid; i < KC * HID; i += NT) {
        sb1[i] = b1[i];
        sW2[i] = W2[i];
    }
    if (tid < KC) sb2[tid] = b2[tid];
    if (tid < KC * 3) sc[tid] = centroids[tid];
    __syncthreads();

    const int warp = tid >> 5, lane = tid & 31;
    const int idxA = blockIdx.x * (2 * NT) + warp * 64 + lane;
    const int idxB = idxA + 32;
    if (idxA >= N) return;
    const bool hasB = idxB < N;

    const float4 pA = d_spos[idxA];
    const float4 pB = d_spos[hasB ? idxB : idxA];

    const int kA = argmin_k(sc, pA.x, pA.y, pA.z);
    const int kB = argmin_k(sc, pB.x, pB.y, pB.z);

    const float2* tbl = reinterpret_cast<const float2*>(tables);
    const unsigned kbaseA = (unsigned)kA * LV;
    const unsigned kbaseB = (unsigned)kB * LV;

    float encA[ENC], encB[ENC];
    float res = 16.0f;
#pragma unroll
    for (int l = 0; l < LV; l++) {
        float a0, a1, b0, b1v;
        hash_level(tbl, (kbaseA + l) * TS, pA.x * res, pA.y * res, pA.z * res, a0, a1);
        hash_level(tbl, (kbaseB + l) * TS, pB.x * res, pB.y * res, pB.z * res, b0, b1v);
        encA[2 * l + 0] = a0;  encA[2 * l + 1] = a1;
        encB[2 * l + 0] = b0;  encB[2 * l + 1] = b1v;
        res *= 2.0f;
    }

    const float dA = mlp_eval(sW1, sb1, sW2, sb2, kA, encA);
    out[__float_as_int(pA.w)] = __expf(dA);
    if (hasB) {
        const float dB = mlp_eval(sW1, sb1, sW2, sb2, kB, encB);
        out[__float_as_int(pB.w)] = __expf(dB);
    }
}

extern "C" void kernel_launch(void* const* d_in, const int* in_sizes, int n_in,
                              void* d_out, int out_size)
{
    const float* positions = (const float*)d_in[0];
    const float* centroids = (const float*)d_in[1];
    const float* tables    = (const float*)d_in[2];
    const float* W1        = (const float*)d_in[3];
    const float* b1        = (const float*)d_in[4];
    const float* W2        = (const float*)d_in[5];
    const float* b2        = (const float*)d_in[6];
    float* out = (float*)d_out;

    const int N = in_sizes[0] / 3;
    const int N4 = N / 4;   // N = 524288, divisible by 4

    k_count<<<(N4 + 255) / 256, 256>>>((const float4*)positions, N4);
    k_scan_a<<<NPART, 256>>>();
    k_scan_c<<<NPART, 256>>>();
    k_scatter<<<(N + 255) / 256, 256>>>(positions, N);
    density_kernel<<<(N + 2 * NT - 1) / (2 * NT), NT>>>(centroids, tables,
                                                        W1, b1, W2, b2, out, N);
}